// round 15
// baseline (speedup 1.0000x reference)
#include <cuda_runtime.h>
#include <cuda_fp16.h>
#include <math.h>
#include <stdint.h>

#define B_    2048
#define S_    128
#define D_    1024
#define DFF_  4096
#define NCAND 32
#define NACT  546

#define K1    D_              // 1024: pure fp16
#define BM    128
#define BN    64
#define BK    64
#define NCH   (K1/BK)         // 16
#define GT    256             // 8 warps: 4m x 2n, warp tile 32x32

#define STAGE_BYTES 24576     // A 16KB + B 8KB
#define SM_TOTAL (2*STAGE_BYTES)   // 48KB -> 4 CTAs/SM

#define NBLK_B 2048
#define NBLK_A 512

// ---------------- scratch ----------------
__device__ __half g_A2[(size_t)B_   * K1];   // 4 MB
__device__ __half g_B2t[(size_t)DFF_ * K1];  // 8 MB, [n][k]

// ---------------- helpers ----------------
__device__ __forceinline__ uint32_t smem_u32(const void* p) {
    uint32_t a;
    asm("{ .reg .u64 t; cvta.to.shared.u64 t, %1; cvt.u32.u64 %0, t; }" : "=r"(a) : "l"(p));
    return a;
}
__device__ __forceinline__ void cp_async16(uint32_t s, const void* g) {
    asm volatile("cp.async.cg.shared.global [%0], [%1], 16;" :: "r"(s), "l"(g));
}
#define CP_COMMIT() asm volatile("cp.async.commit_group;" ::: "memory")
template <int N>
__device__ __forceinline__ void cp_wait() {
    asm volatile("cp.async.wait_group %0;" :: "n"(N) : "memory");
}
__device__ __forceinline__ void ldsm_x4(uint32_t* r, uint32_t addr) {
    asm volatile("ldmatrix.sync.aligned.m8n8.x4.shared.b16 {%0,%1,%2,%3}, [%4];"
                 : "=r"(r[0]), "=r"(r[1]), "=r"(r[2]), "=r"(r[3]) : "r"(addr));
}
__device__ __forceinline__ void mma16816(float* d, const uint32_t* a, uint32_t b0, uint32_t b1) {
    asm volatile("mma.sync.aligned.m16n8k16.row.col.f32.f16.f16.f32 "
                 "{%0,%1,%2,%3}, {%4,%5,%6,%7}, {%8,%9}, {%0,%1,%2,%3};"
                 : "+f"(d[0]), "+f"(d[1]), "+f"(d[2]), "+f"(d[3])
                 : "r"(a[0]), "r"(a[1]), "r"(a[2]), "r"(a[3]), "r"(b0), "r"(b1));
}
__device__ __forceinline__ float gelu_exact(float x) {
    return 0.5f * x * (1.0f + erff(x * 0.70710678118654752f));
}
__device__ __forceinline__ uint32_t swz(int r, int c2) {
    return (uint32_t)(r * 128 + ((c2 * 16) ^ ((r & 7) * 16)));
}
__device__ __forceinline__ uint32_t pack_h2(__half x, __half y) {
    __half2 v; v.x = x; v.y = y;
    return *(uint32_t*)&v;
}

// ---------------- kernel 1: fused conv (B first, then A) ----------------
__global__ void conv_kernel(const int* __restrict__ cand,
                            const float* __restrict__ encode,
                            const float* __restrict__ W1,
                            const float* __restrict__ b2,
                            float* __restrict__ out) {
    if (blockIdx.x < NBLK_B) {
        __shared__ float tile[32][68];
        const int bb = blockIdx.x;
        const int n0 = (bb & 63) * 64;
        const int k0 = (bb >> 6) * 32;
        {
            const int r  = threadIdx.x >> 4;
            const int c4 = (threadIdx.x & 15) * 4;
            #pragma unroll
            for (int rr = r; rr < 32; rr += 16) {
                float4 v = *(const float4*)&W1[(size_t)(k0 + rr) * DFF_ + n0 + c4];
                *(float4*)&tile[rr][c4] = v;
            }
        }
        __syncthreads();
        {
            const int n  = threadIdx.x & 63;
            const int kq = (threadIdx.x >> 6) * 8;
            uint32_t hi[4];
            #pragma unroll
            for (int i = 0; i < 4; i++) {
                hi[i] = pack_h2(__float2half_rn(tile[kq + 2 * i][n]),
                                __float2half_rn(tile[kq + 2 * i + 1][n]));
            }
            *(uint4*)(g_B2t + (size_t)(n0 + n) * K1 + k0 + kq) = *(uint4*)hi;
        }
    } else {
        const int b0 = (blockIdx.x - NBLK_B) * 4;
        __shared__ int srow[4];
        const int w = threadIdx.x >> 5, lane = threadIdx.x & 31;
        if (w < 4) {
            int c = cand[(b0 + w) * NCAND + lane];
            unsigned m = __ballot_sync(0xffffffffu, c >= NACT);
            if (lane == 0) {
                srow[w] = (S_ - NCAND) + (__ffs(m) - 1);
                out[b0 + w] = b2[0];
            }
        }
        __syncthreads();
        const int i = threadIdx.x;
        #pragma unroll
        for (int r = 0; r < 4; r++) {
            const int b = b0 + r;
            float4 a = ((const float4*)(encode + ((size_t)b * S_ + srow[r]) * D_))[i];
            uint2 hv;
            hv.x = pack_h2(__float2half_rn(a.x), __float2half_rn(a.y));
            hv.y = pack_h2(__float2half_rn(a.z), __float2half_rn(a.w));
            *(uint2*)(g_A2 + (size_t)b * K1 + 4 * i) = hv;
        }
    }
    cudaTriggerProgrammaticLaunchCompletion();
}

// ---------------- kernel 2: fp16 HMMA GEMM, 128x64 tile, 2-stage, 4 CTAs/SM ----------------
__global__ __launch_bounds__(GT, 4)
void gemm_kernel(const float* __restrict__ b1,
                 const float* __restrict__ W2,
                 float* __restrict__ out) {
    extern __shared__ char smem[];
    const uint32_t sb = smem_u32(smem);
    const int tid  = threadIdx.x;
    const int wid  = tid >> 5;
    const int lane = tid & 31;
    const int wm = wid >> 1;     // 0..3 (32 rows each)
    const int wn = wid & 1;      // 0..1 (32 cols each)
    const int bn = blockIdx.x;   // 0..63
    const int bm = blockIdx.y;   // 0..15

    // ---- cp.async mapping: A 4 chunks + B 2 chunks per thread per stage
    const int lr  = tid >> 3;    // 0..31
    const int lc2 = tid & 7;
    const char* aPtr = (const char*)(g_A2  + (size_t)(bm * BM + lr) * K1 + lc2 * 8);
    const char* bPtr = (const char*)(g_B2t + (size_t)(bn * BN + lr) * K1 + lc2 * 8);
    const uint32_t aSw0 = swz(lr, lc2);          // +i*32 rows => +i*4096 in smem
    const uint32_t bSw0 = aSw0 + 16384;

    // ---- ldmatrix address constants
    const int l15 = lane & 15;
    const uint32_t xb  = (uint32_t)(l15 & 7) * 16;
    const uint32_t hlx = ((uint32_t)(lane >> 4) * 16) ^ (xb & 16);
    const uint32_t xh  = xb & 0x60;
    const uint32_t aBase = sb + (uint32_t)(wm * 32 + l15) * 128 + hlx;
    const uint32_t bBase = sb + (uint32_t)(wn * 32 + l15) * 128 + hlx + 16384;
    const uint32_t xh0 = 0 ^ xh, xh1 = 32 ^ xh, xh2 = 64 ^ xh, xh3 = 96 ^ xh;

    float acc[2][4][4];
    #pragma unroll
    for (int i = 0; i < 2; i++)
        #pragma unroll
        for (int j = 0; j < 4; j++)
            #pragma unroll
            for (int r = 0; r < 4; r++) acc[i][j][r] = 0.f;

    cudaGridDependencySynchronize();

    // R32 = 32 gmem rows = 32*K1*2 bytes (compile-time)
    #define R32 ((size_t)32 * K1 * 2)
    #define LOAD_STAGE(buf, c)                                                       \
        do {                                                                         \
            _Pragma("unroll")                                                        \
            for (int i = 0; i < 4; i++)                                              \
                cp_async16(sb + (buf) * STAGE_BYTES + aSw0 + i * 4096,               \
                           aPtr + i * R32 + (c) * 128);                              \
            _Pragma("unroll")                                                        \
            for (int i = 0; i < 2; i++)                                              \
                cp_async16(sb + (buf) * STAGE_BYTES + bSw0 + i * 4096,               \
                           bPtr + i * R32 + (c) * 128);                              \
            CP_COMMIT();                                                             \
        } while (0)

    LOAD_STAGE(0, 0);
    LOAD_STAGE(1, 1);

    #pragma unroll
    for (int c = 0; c < NCH; c++) {
        cp_wait<1>();        // stage c arrived (c+1 may still be in flight)
        __syncthreads();

        const uint32_t stg = (uint32_t)((c & 1) * STAGE_BYTES);
        const uint32_t ksofs[4] = {stg + xh0, stg + xh1, stg + xh2, stg + xh3};

        #pragma unroll
        for (int ks = 0; ks < 4; ks++) {
            uint32_t afr[2][4], bfr[2][4];
            #pragma unroll
            for (int mt = 0; mt < 2; mt++) ldsm_x4(afr[mt], aBase + ksofs[ks] + mt * 2048);
            #pragma unroll
            for (int u = 0; u < 2; u++)    ldsm_x4(bfr[u],  bBase + ksofs[ks] + u * 2048);
            #pragma unroll
            for (int mt = 0; mt < 2; mt++)
                #pragma unroll
                for (int nt = 0; nt < 4; nt++)
                    mma16816(acc[mt][nt], afr[mt],
                             bfr[nt >> 1][nt & 1], bfr[nt >> 1][(nt & 1) + 2]);
        }

        if (c + 2 < NCH) {
            __syncthreads();             // all warps done reading buf (c&1)
            LOAD_STAGE((c & 1), c + 2);  // refill it
        }
    }

    // ---- Epilogue: bias + exact gelu + dot W2, reduce, atomicAdd ----
    const int qn = lane & 3;
    const int qr = lane >> 2;
    float bia[4][2], w2v[4][2];
    #pragma unroll
    for (int nt = 0; nt < 4; nt++) {
        int n = bn * BN + wn * 32 + nt * 8 + qn * 2;
        bia[nt][0] = __ldg(&b1[n]);     bia[nt][1] = __ldg(&b1[n + 1]);
        w2v[nt][0] = __ldg(&W2[n]);     w2v[nt][1] = __ldg(&W2[n + 1]);
    }
    #pragma unroll
    for (int mt = 0; mt < 2; mt++) {
        float p0 = 0.f, p1 = 0.f;
        #pragma unroll
        for (int nt = 0; nt < 4; nt++) {
            const float* d = acc[mt][nt];
            p0 = fmaf(gelu_exact(d[0] + bia[nt][0]), w2v[nt][0], p0);
            p0 = fmaf(gelu_exact(d[1] + bia[nt][1]), w2v[nt][1], p0);
            p1 = fmaf(gelu_exact(d[2] + bia[nt][0]), w2v[nt][0], p1);
            p1 = fmaf(gelu_exact(d[3] + bia[nt][1]), w2v[nt][1], p1);
        }
        p0 += __shfl_xor_sync(0xffffffffu, p0, 1);
        p0 += __shfl_xor_sync(0xffffffffu, p0, 2);
        p1 += __shfl_xor_sync(0xffffffffu, p1, 1);
        p1 += __shfl_xor_sync(0xffffffffu, p1, 2);
        if (qn == 0) {
            int m = bm * BM + wm * 32 + mt * 16 + qr;
            atomicAdd(&out[m], p0);
            atomicAdd(&out[m + 8], p1);
        }
    }
}

// ---------------- launcher ----------------
extern "C" void kernel_launch(void* const* d_in, const int* in_sizes, int n_in,
                              void* d_out, int out_size) {
    const int*   cand   = (const int*)d_in[0];
    const float* encode = (const float*)d_in[1];
    const float* W1     = (const float*)d_in[2];
    const float* b1     = (const float*)d_in[3];
    const float* W2     = (const float*)d_in[4];
    const float* b2     = (const float*)d_in[5];
    float* out = (float*)d_out;

    static int smem_set = 0;
    if (!smem_set) {
        cudaFuncSetAttribute(gemm_kernel, cudaFuncAttributeMaxDynamicSharedMemorySize, SM_TOTAL);
        smem_set = 1;
    }

    conv_kernel<<<NBLK_B + NBLK_A, 256>>>(cand, encode, W1, b2, out);

    cudaLaunchConfig_t cfg = {};
    cfg.gridDim  = dim3(DFF_ / BN, B_ / BM, 1);   // (64, 16)
    cfg.blockDim = dim3(GT, 1, 1);
    cfg.dynamicSmemBytes = SM_TOTAL;
    cfg.stream = 0;
    cudaLaunchAttribute attrs[1];
    attrs[0].id = cudaLaunchAttributeProgrammaticStreamSerialization;
    attrs[0].val.programmaticStreamSerializationAllowed = 1;
    cfg.attrs = attrs;
    cfg.numAttrs = 1;
    cudaLaunchKernelEx(&cfg, gemm_kernel, b1, W2, out);
}